// round 10
// baseline (speedup 1.0000x reference)
#include <cuda_runtime.h>

// Problem constants
#define BATCH 8
#define IMH 180
#define IMW 180
#define NF 24
#define NB 31
#define NPIX (IMH * IMW)          // 32400
#define NTOT (BATCH * NPIX)       // 259200
#define N4   (NTOT / 4)           // 64800

#define TILE 32
#define UT 40                      // u tile (TILE + 2*4)
#define PT 36                      // phi tile (TILE + 2*2)

// LUT for phi(x) = sum_j w_j exp(-50 (x-mu_j)^2), x in [XMIN, XMAX]
#define NCELL 1024
#define XMIN (-2.0f)
#define XMAX (2.0f)
#define LUT_H ((XMAX - XMIN) / (float)NCELL)
#define LUT_INVH ((float)NCELL / (XMAX - XMIN))

#define NTHR 512                   // 4 filter-groups of 128 threads
#define NFG  6                     // filters per group

typedef unsigned long long u64t;

__device__ float  g_partials[64];
__device__ float2 g_lut[NCELL];

// ---- f32x2 helpers ----
__device__ __forceinline__ u64t pk2(float lo, float hi) {
    u64t r; asm("mov.b64 %0, {%1, %2};" : "=l"(r) : "f"(lo), "f"(hi)); return r;
}
__device__ __forceinline__ void fma2(u64t& d, u64t a, u64t b) {
    asm("fma.rn.f32x2 %0, %1, %2, %3;" : "=l"(d) : "l"(a), "l"(b), "l"(d));
}
__device__ __forceinline__ float2 up2(u64t v) {
    float2 r; asm("mov.b64 {%0, %1}, %2;" : "=f"(r.x), "=f"(r.y) : "l"(v)); return r;
}

// ---------------------------------------------------------------------------
// k_init: blocks [0,4) build the 1024-cell LUT; blocks [4,68) compute
// weighted partial sums for M: sum(u_sigma)*9 = sum_p u[p]*cnt(p).
// ---------------------------------------------------------------------------
__global__ void k_init(const float* __restrict__ u,
                       const float* __restrict__ mu,
                       const float* __restrict__ wts) {
    const int tid = threadIdx.x;
    if (blockIdx.x < 4) {
        int i = blockIdx.x * 256 + tid;        // 0..1023
        float x0 = XMIN + (float)i * LUT_H;
        float x1 = x0 + LUT_H;
        float p0 = 0.f, p1 = 0.f;
        #pragma unroll 1
        for (int j = 0; j < NB; j++) {
            float m = mu[j], w = wts[j];
            float d0 = x0 - m, d1 = x1 - m;
            p0 += w * expf(-50.f * d0 * d0);
            p1 += w * expf(-50.f * d1 * d1);
        }
        g_lut[i] = make_float2(p0, p1 - p0);
    } else {
        __shared__ float sm[256];
        const int pb = blockIdx.x - 4;         // 0..63
        float s = 0.f;
        for (int i = pb * 256 + tid; i < N4; i += 64 * 256) {
            int idx4 = i * 4;
            int p = idx4 % NPIX;
            int y = p / IMW;
            int x0 = p - y * IMW;
            float wy = 3.f - (y == 0 ? 1.f : 0.f) - (y == IMH - 1 ? 1.f : 0.f);
            float4 v = ((const float4*)u)[i];
            float w0 = (x0 == 0) ? 2.f : 3.f;
            float w3 = (x0 == IMW - 4) ? 2.f : 3.f;
            s += wy * (v.x * w0 + v.y * 3.f + v.z * 3.f + v.w * w3);
        }
        sm[tid] = s;
        __syncthreads();
        for (int o = 128; o > 0; o >>= 1) {
            if (tid < o) sm[tid] += sm[tid + o];
            __syncthreads();
        }
        if (tid == 0) g_partials[pb] = sm[0];
    }
}

// ---------------------------------------------------------------------------
// k_main: fused TNRD stage per 32x32 tile; 4 filter-groups of 128 threads,
// double-buffered phi, 1 named barrier per filter. Convolutions use packed
// fma.rn.f32x2: column-pair accumulators, even input pairs free via float4
// register aliasing, odd pairs packed, taps DUPLICATED in smem so broadcast
// LDS.64 yields (t,t) multiplier pairs (flip for adjoint = reversed index).
// Dynamic smem layout (bytes):
//   [0, 8192)        sLUT  : 1024 x float2
//   [8192, 14592)    sU    : 40x40
//   [14592, 19776)   sUS   : 36x36 (u_sigma/M, zeroed outside image)
//   [19776, 61248)   sPhi  : 8 buffers of 36x36 (2 per group)
//   [61248, 67008)   sFd   : 24 filters x 5 rows x (5 taps x 2 dup + 2 pad)
// ---------------------------------------------------------------------------
#define OFF_LUT 0
#define OFF_U   8192
#define OFF_US  14592
#define OFF_PHI 19776
#define OFF_F   61248
#define PHI_STRIDE 5184
#define SMEM_BYTES 67008

__global__ __launch_bounds__(NTHR, 2) void k_main(
    const float* __restrict__ u,
    const float* __restrict__ f,
    const float* __restrict__ filt,
    const float* __restrict__ lam,
    float* __restrict__ out)
{
    extern __shared__ char smem[];
    float2* sLUT = (float2*)(smem + OFF_LUT);
    float*  sU   = (float*)(smem + OFF_U);
    float*  sUS  = (float*)(smem + OFF_US);
    float*  sFd  = (float*)(smem + OFF_F);
    __shared__ float s_invM;

    const int b   = blockIdx.z;
    const int oy0 = blockIdx.y * TILE;
    const int ox0 = blockIdx.x * TILE;
    const int tid = threadIdx.x;
    const int g   = tid >> 7;          // filter-group 0..3
    const int gt  = tid & 127;         // lane within group

    const float* ub = u + b * NPIX;
    const float* fb = f + b * NPIX;
    float* ob = out + b * NPIX;

    float* phiBuf[2] = { (float*)(smem + OFF_PHI + (2 * g + 0) * PHI_STRIDE),
                         (float*)(smem + OFF_PHI + (2 * g + 1) * PHI_STRIDE) };

    // ---- invM: single-warp shuffle reduction over 64 partials ----
    if (tid < 32) {
        float s = g_partials[tid] + g_partials[tid + 32];
        #pragma unroll
        for (int o = 16; o > 0; o >>= 1)
            s += __shfl_down_sync(0xffffffffu, s, o);
        if (tid == 0)
            s_invM = 1.f / (s / (9.f * (float)NTOT) + 0.001f);
    }

    // ---- cooperative loads ----
    {
        const float4* lg = (const float4*)g_lut;
        float4* ls = (float4*)sLUT;
        ls[tid] = lg[tid];                         // 512 float4 = whole LUT
    }
    // filter taps, duplicated: sFd[fi*60 + ky*12 + kx*2 + {0,1}] = F[fi][ky][kx]
    for (int i = tid; i < NF * 25; i += NTHR) {
        int fi = i / 25, r25 = i - fi * 25;
        int ky = r25 / 5, kx = r25 - ky * 5;
        float v = filt[i];
        sFd[fi * 60 + ky * 12 + kx * 2 + 0] = v;
        sFd[fi * 60 + ky * 12 + kx * 2 + 1] = v;
    }
    for (int i = tid; i < UT * UT; i += NTHR) {
        int r = i / UT, c = i - r * UT;
        int gy = oy0 - 4 + r, gx = ox0 - 4 + c;
        float v = 0.f;
        if ((unsigned)gy < IMH && (unsigned)gx < IMW) v = ub[gy * IMW + gx];
        sU[i] = v;
    }
    __syncthreads();

    const float invM = s_invM;

    // ---- u_sigma/M on phi tile; zero outside image ----
    for (int i = tid; i < PT * PT; i += NTHR) {
        int r = i / PT, c = i - r * PT;
        int gy = oy0 - 2 + r, gx = ox0 - 2 + c;
        float v = 0.f;
        if ((unsigned)gy < IMH && (unsigned)gx < IMW) {
            float s0 = sU[(r + 1) * UT + c + 1] + sU[(r + 1) * UT + c + 2] + sU[(r + 1) * UT + c + 3];
            float s1 = sU[(r + 2) * UT + c + 1] + sU[(r + 2) * UT + c + 2] + sU[(r + 2) * UT + c + 3];
            float s2 = sU[(r + 3) * UT + c + 1] + sU[(r + 3) * UT + c + 2] + sU[(r + 3) * UT + c + 3];
            v = (s0 + s1 + s2) * (1.f / 9.f) * invM;
        }
        sUS[i] = v;
    }
    __syncthreads();

    // ---- per-thread fixed strips ----
    const int ffr0 = (gt / 9) * 3;        // forward: 3x4 strip, 108 active
    const int ffc0 = (gt % 9) * 4;
    const bool fwd_on = (gt < 108);
    const int qr0 = (gt >> 3) * 2;        // adjoint: 2x4 strip, 128 active
    const int qc0 = (gt & 7) * 4;

    u64t accA[2] = {0ull, 0ull};          // (a0,a1) per adjoint row
    u64t accB[2] = {0ull, 0ull};          // (a2,a3) per adjoint row

    const int fbase = g * NFG;

    #define GBAR() asm volatile("bar.sync %0, %1;" :: "r"(g + 1), "r"(128) : "memory")

    // ---- forward: 5x5 conv (f32x2) + LUT phi + scale -> DST ----
    #define FWD(FI, DST)                                                      \
        if (fwd_on) {                                                         \
            u64t a01[3] = {0ull, 0ull, 0ull};                                 \
            u64t a23[3] = {0ull, 0ull, 0ull};                                 \
            _Pragma("unroll")                                                 \
            for (int ky = 0; ky < 5; ky++) {                                  \
                const u64t* tp = (const u64t*)&sFd[(FI) * 60 + ky * 12];      \
                u64t t0 = tp[0], t1 = tp[1], t2 = tp[2], t3 = tp[3], t4 = tp[4]; \
                _Pragma("unroll")                                             \
                for (int rr = 0; rr < 3; rr++) {                              \
                    const float4* rp = (const float4*)&sU[(ffr0 + rr + ky) * UT + ffc0]; \
                    float4 A = rp[0], B = rp[1];                              \
                    u64t e01 = pk2(A.x, A.y), e23 = pk2(A.z, A.w);            \
                    u64t e45 = pk2(B.x, B.y), e67 = pk2(B.z, B.w);            \
                    u64t o12 = pk2(A.y, A.z), o34 = pk2(A.w, B.x);            \
                    u64t o56 = pk2(B.y, B.z);                                 \
                    fma2(a01[rr], e01, t0); fma2(a23[rr], e23, t0);           \
                    fma2(a01[rr], o12, t1); fma2(a23[rr], o34, t1);           \
                    fma2(a01[rr], e23, t2); fma2(a23[rr], e45, t2);           \
                    fma2(a01[rr], o34, t3); fma2(a23[rr], o56, t3);           \
                    fma2(a01[rr], e45, t4); fma2(a23[rr], e67, t4);           \
                }                                                             \
            }                                                                 \
            _Pragma("unroll")                                                 \
            for (int rr = 0; rr < 3; rr++) {                                  \
                float2 c01 = up2(a01[rr]), c23 = up2(a23[rr]);                \
                float conv[4] = {c01.x, c01.y, c23.x, c23.y};                 \
                float4 usv = *(const float4*)&sUS[(ffr0 + rr) * PT + ffc0];   \
                float us[4] = {usv.x, usv.y, usv.z, usv.w};                   \
                float res[4];                                                 \
                _Pragma("unroll")                                             \
                for (int k = 0; k < 4; k++) {                                 \
                    float xc = fminf(fmaxf(conv[k], XMIN), XMAX);             \
                    float tt = (xc - XMIN) * LUT_INVH;                        \
                    int ii = (int)tt;                                         \
                    ii = min(ii, NCELL - 1);                                  \
                    float frac = tt - (float)ii;                              \
                    float2 cell = sLUT[ii];                                   \
                    res[k] = us[k] * fmaf(cell.y, frac, cell.x);              \
                }                                                             \
                *(float4*)&(DST)[(ffr0 + rr) * PT + ffc0] =                   \
                    make_float4(res[0], res[1], res[2], res[3]);              \
            }                                                                 \
        }

    // ---- adjoint: flipped 5x5 conv (f32x2); taps = tp[4-j] of row 4-ky ----
    #define ADJ(FI, SRC)                                                      \
        {                                                                     \
            _Pragma("unroll")                                                 \
            for (int ky = 0; ky < 5; ky++) {                                  \
                const u64t* tp = (const u64t*)&sFd[(FI) * 60 + (4 - ky) * 12];\
                u64t t0 = tp[4], t1 = tp[3], t2 = tp[2], t3 = tp[1], t4 = tp[0]; \
                _Pragma("unroll")                                             \
                for (int rr = 0; rr < 2; rr++) {                              \
                    const float4* rp = (const float4*)&(SRC)[(qr0 + rr + ky) * PT + qc0]; \
                    float4 A = rp[0], B = rp[1];                              \
                    u64t e01 = pk2(A.x, A.y), e23 = pk2(A.z, A.w);            \
                    u64t e45 = pk2(B.x, B.y), e67 = pk2(B.z, B.w);            \
                    u64t o12 = pk2(A.y, A.z), o34 = pk2(A.w, B.x);            \
                    u64t o56 = pk2(B.y, B.z);                                 \
                    fma2(accA[rr], e01, t0); fma2(accB[rr], e23, t0);         \
                    fma2(accA[rr], o12, t1); fma2(accB[rr], o34, t1);         \
                    fma2(accA[rr], e23, t2); fma2(accB[rr], e45, t2);         \
                    fma2(accA[rr], o34, t3); fma2(accB[rr], o56, t3);         \
                    fma2(accA[rr], e45, t4); fma2(accB[rr], e67, t4);         \
                }                                                             \
            }                                                                 \
        }

    // ---- pipelined loop: 1 named barrier per filter ----
    FWD(fbase + 0, phiBuf[0])
    GBAR();
    #pragma unroll 1
    for (int kf = 1; kf < NFG; kf++) {
        FWD(fbase + kf, phiBuf[kf & 1])
        ADJ(fbase + kf - 1, phiBuf[(kf - 1) & 1])
        GBAR();
    }
    ADJ(fbase + NFG - 1, phiBuf[(NFG - 1) & 1])
    #undef FWD
    #undef ADJ
    #undef GBAR

    // ---- unpack accumulators ----
    float acc[8];
    {
        float2 r0a = up2(accA[0]), r0b = up2(accB[0]);
        float2 r1a = up2(accA[1]), r1b = up2(accB[1]);
        acc[0] = r0a.x; acc[1] = r0a.y; acc[2] = r0b.x; acc[3] = r0b.y;
        acc[4] = r1a.x; acc[5] = r1a.y; acc[6] = r1b.x; acc[7] = r1b.y;
    }

    // ---- combine group accumulators (groups 1..3 -> smem; group 0 sums) ----
    __syncthreads();                 // all groups done with their phi buffers
    if (g > 0) {
        float4* buf = (float4*)(smem + OFF_PHI + (2 * g) * PHI_STRIDE);
        buf[gt * 2 + 0] = make_float4(acc[0], acc[1], acc[2], acc[3]);
        buf[gt * 2 + 1] = make_float4(acc[4], acc[5], acc[6], acc[7]);
    }
    __syncthreads();

    // ---- epilogue: reaction + clip (group 0) ----
    if (g == 0) {
        #pragma unroll
        for (int gg = 1; gg < 4; gg++) {
            const float4* buf = (const float4*)(smem + OFF_PHI + (2 * gg) * PHI_STRIDE);
            float4 c0 = buf[gt * 2 + 0], c1 = buf[gt * 2 + 1];
            acc[0] += c0.x; acc[1] += c0.y; acc[2] += c0.z; acc[3] += c0.w;
            acc[4] += c1.x; acc[5] += c1.y; acc[6] += c1.z; acc[7] += c1.w;
        }
        const float lambda = lam[0];
        #pragma unroll
        for (int rr = 0; rr < 2; rr++) {
            const int gy = oy0 + qr0 + rr;
            if (gy < IMH) {
                float4 uv4 = *(const float4*)&sU[(qr0 + rr + 4) * UT + qc0 + 4];
                float uvs[4] = {uv4.x, uv4.y, uv4.z, uv4.w};
                #pragma unroll
                for (int k = 0; k < 4; k++) {
                    int gx = ox0 + qc0 + k;
                    if (gx < IMW) {
                        float uv = uvs[k];
                        float fv = fb[gy * IMW + gx];
                        float reac = lambda * (uv - fv) / (uv * uv + 1e-3f);
                        float o = uv - acc[rr * 4 + k] - reac;
                        o = fminf(fmaxf(o, 0.f), 1.f);
                        ob[gy * IMW + gx] = o;
                    }
                }
            }
        }
    }
}

// ---------------------------------------------------------------------------
// Launch
// ---------------------------------------------------------------------------
extern "C" void kernel_launch(void* const* d_in, const int* in_sizes, int n_in,
                              void* d_out, int out_size) {
    const float* u    = (const float*)d_in[0];
    const float* f    = (const float*)d_in[1];
    const float* filt = (const float*)d_in[2];
    const float* lam  = (const float*)d_in[3];
    const float* mu   = (const float*)d_in[4];
    const float* wts  = (const float*)d_in[5];
    float* out = (float*)d_out;

    // SMEM_BYTES > 48KB needs the opt-in attribute. Set once, outside graph
    // capture (the harness's correctness call precedes capture).
    static bool attr_set = false;
    if (!attr_set) {
        cudaFuncSetAttribute(k_main, cudaFuncAttributeMaxDynamicSharedMemorySize,
                             SMEM_BYTES);
        attr_set = true;
    }

    k_init<<<68, 256>>>(u, mu, wts);
    dim3 grid((IMW + TILE - 1) / TILE, (IMH + TILE - 1) / TILE, BATCH);
    k_main<<<grid, NTHR, SMEM_BYTES>>>(u, f, filt, lam, out);
}

// round 11
// speedup vs baseline: 1.2304x; 1.2304x over previous
#include <cuda_runtime.h>

// Problem constants
#define BATCH 8
#define IMH 180
#define IMW 180
#define NF 24
#define NB 31
#define NPIX (IMH * IMW)          // 32400
#define NTOT (BATCH * NPIX)       // 259200
#define N4   (NTOT / 4)           // 64800

#define TILE 32
#define UT 40                      // u tile rows (TILE + 2*4)
#define PT 36                      // phi tile rows (TILE + 2*2)
#define RS 44                      // padded row stride (words): 3*44 % 32 == 4 -> conflict-free phases

// LUT for phi(x) = sum_j w_j exp(-50 (x-mu_j)^2), x in [XMIN, XMAX]
#define NCELL 1024
#define XMIN (-2.0f)
#define XMAX (2.0f)
#define LUT_H ((XMAX - XMIN) / (float)NCELL)
#define LUT_INVH ((float)NCELL / (XMAX - XMIN))

#define NTHR 512                   // 4 filter-groups of 128 threads
#define NFG  6                     // filters per group

__device__ float  g_partials[64];
__device__ float2 g_lut[NCELL];

// ---------------------------------------------------------------------------
// k_init: blocks [0,4) build the 1024-cell LUT; blocks [4,68) compute
// weighted partial sums for M: sum(u_sigma)*9 = sum_p u[p]*cnt(p).
// ---------------------------------------------------------------------------
__global__ void k_init(const float* __restrict__ u,
                       const float* __restrict__ mu,
                       const float* __restrict__ wts) {
    const int tid = threadIdx.x;
    if (blockIdx.x < 4) {
        int i = blockIdx.x * 256 + tid;        // 0..1023
        float x0 = XMIN + (float)i * LUT_H;
        float x1 = x0 + LUT_H;
        float p0 = 0.f, p1 = 0.f;
        #pragma unroll 1
        for (int j = 0; j < NB; j++) {
            float m = mu[j], w = wts[j];
            float d0 = x0 - m, d1 = x1 - m;
            p0 += w * expf(-50.f * d0 * d0);
            p1 += w * expf(-50.f * d1 * d1);
        }
        g_lut[i] = make_float2(p0, p1 - p0);
    } else {
        __shared__ float sm[256];
        const int pb = blockIdx.x - 4;         // 0..63
        float s = 0.f;
        for (int i = pb * 256 + tid; i < N4; i += 64 * 256) {
            int idx4 = i * 4;
            int p = idx4 % NPIX;
            int y = p / IMW;
            int x0 = p - y * IMW;
            float wy = 3.f - (y == 0 ? 1.f : 0.f) - (y == IMH - 1 ? 1.f : 0.f);
            float4 v = ((const float4*)u)[i];
            float w0 = (x0 == 0) ? 2.f : 3.f;
            float w3 = (x0 == IMW - 4) ? 2.f : 3.f;
            s += wy * (v.x * w0 + v.y * 3.f + v.z * 3.f + v.w * w3);
        }
        sm[tid] = s;
        __syncthreads();
        for (int o = 128; o > 0; o >>= 1) {
            if (tid < o) sm[tid] += sm[tid + o];
            __syncthreads();
        }
        if (tid == 0) g_partials[pb] = sm[0];
    }
}

// ---------------------------------------------------------------------------
// k_main: fused TNRD stage per 32x32 tile; 4 filter-groups of 128 threads,
// double-buffered phi, 1 named barrier per filter. All 2-D smem tiles use a
// padded 44-word row stride so every LDS.128/STS.128 phase is bank-disjoint.
// Dynamic smem layout (bytes):
//   [0, 8192)        sLUT  : 1024 x float2
//   [8192, 15232)    sU    : 40 rows x 44 stride
//   [15232, 21568)   sUS   : 36 rows x 44 stride (u_sigma/M, 0 outside image)
//   [21568, 72256)   sPhi  : 8 buffers of 36 rows x 44 stride (2 per group)
//   [72256, 76096)   sF    : 24 filters x 5 rows x 8 floats (padded)
// ---------------------------------------------------------------------------
#define OFF_LUT 0
#define OFF_U   8192
#define OFF_US  15232
#define OFF_PHI 21568
#define OFF_F   72256
#define PHI_STRIDE (PT * RS * 4)   // 6336 bytes
#define SMEM_BYTES 76096

__global__ __launch_bounds__(NTHR, 2) void k_main(
    const float* __restrict__ u,
    const float* __restrict__ f,
    const float* __restrict__ filt,
    const float* __restrict__ lam,
    float* __restrict__ out)
{
    extern __shared__ char smem[];
    float2* sLUT = (float2*)(smem + OFF_LUT);
    float*  sU   = (float*)(smem + OFF_U);
    float*  sUS  = (float*)(smem + OFF_US);
    float*  sF   = (float*)(smem + OFF_F);
    __shared__ float s_invM;

    const int b   = blockIdx.z;
    const int oy0 = blockIdx.y * TILE;
    const int ox0 = blockIdx.x * TILE;
    const int tid = threadIdx.x;
    const int g   = tid >> 7;          // filter-group 0..3
    const int gt  = tid & 127;         // lane within group

    const float* ub = u + b * NPIX;
    const float* fb = f + b * NPIX;
    float* ob = out + b * NPIX;

    float* phiBuf[2] = { (float*)(smem + OFF_PHI + (2 * g + 0) * PHI_STRIDE),
                         (float*)(smem + OFF_PHI + (2 * g + 1) * PHI_STRIDE) };

    // ---- invM: single-warp shuffle reduction over 64 partials ----
    if (tid < 32) {
        float s = g_partials[tid] + g_partials[tid + 32];
        #pragma unroll
        for (int o = 16; o > 0; o >>= 1)
            s += __shfl_down_sync(0xffffffffu, s, o);
        if (tid == 0)
            s_invM = 1.f / (s / (9.f * (float)NTOT) + 0.001f);
    }

    // ---- cooperative loads ----
    {
        const float4* lg = (const float4*)g_lut;
        float4* ls = (float4*)sLUT;
        ls[tid] = lg[tid];                         // 512 float4 = whole LUT
    }
    for (int i = tid; i < NF * 40; i += NTHR) sF[i] = 0.f;   // pad lanes
    __syncthreads();
    for (int i = tid; i < NF * 25; i += NTHR) {
        int fi = i / 25, r25 = i - fi * 25;
        int ky = r25 / 5, kx = r25 - ky * 5;
        sF[fi * 40 + ky * 8 + kx] = filt[i];
    }
    for (int i = tid; i < UT * UT; i += NTHR) {    // 1600 logical u cells
        int r = i / UT, c = i - r * UT;
        int gy = oy0 - 4 + r, gx = ox0 - 4 + c;
        float v = 0.f;
        if ((unsigned)gy < IMH && (unsigned)gx < IMW) v = ub[gy * IMW + gx];
        sU[r * RS + c] = v;
    }
    __syncthreads();

    const float invM = s_invM;

    // ---- u_sigma/M on phi tile; zero outside image ----
    for (int i = tid; i < PT * PT; i += NTHR) {
        int r = i / PT, c = i - r * PT;
        int gy = oy0 - 2 + r, gx = ox0 - 2 + c;
        float v = 0.f;
        if ((unsigned)gy < IMH && (unsigned)gx < IMW) {
            float s0 = sU[(r + 1) * RS + c + 1] + sU[(r + 1) * RS + c + 2] + sU[(r + 1) * RS + c + 3];
            float s1 = sU[(r + 2) * RS + c + 1] + sU[(r + 2) * RS + c + 2] + sU[(r + 2) * RS + c + 3];
            float s2 = sU[(r + 3) * RS + c + 1] + sU[(r + 3) * RS + c + 2] + sU[(r + 3) * RS + c + 3];
            v = (s0 + s1 + s2) * (1.f / 9.f) * invM;
        }
        sUS[r * RS + c] = v;
    }
    __syncthreads();

    // ---- per-thread fixed strips ----
    const int ffr0 = (gt / 9) * 3;        // forward: 3x4 strip, 108 active
    const int ffc0 = (gt % 9) * 4;
    const bool fwd_on = (gt < 108);
    const int qr0 = (gt >> 3) * 2;        // adjoint: 2x4 strip, 128 active
    const int qc0 = (gt & 7) * 4;

    float acc[8];
    #pragma unroll
    for (int k = 0; k < 8; k++) acc[k] = 0.f;

    const int fbase = g * NFG;

    #define GBAR() asm volatile("bar.sync %0, %1;" :: "r"(g + 1), "r"(128) : "memory")

    // ---- forward: 5x5 conv (ky-major, vector taps) + LUT phi + scale ----
    #define FWD(FI, DST)                                                      \
        if (fwd_on) {                                                         \
            const float* Fp = &sF[(FI) * 40];                                 \
            float a[12];                                                      \
            _Pragma("unroll")                                                 \
            for (int k = 0; k < 12; k++) a[k] = 0.f;                          \
            _Pragma("unroll")                                                 \
            for (int ky = 0; ky < 5; ky++) {                                  \
                float4 tq = *(const float4*)&Fp[ky * 8];                      \
                float t4v = Fp[ky * 8 + 4];                                   \
                _Pragma("unroll")                                             \
                for (int rr = 0; rr < 3; rr++) {                              \
                    const float4* rp = (const float4*)&sU[(ffr0 + rr + ky) * RS + ffc0]; \
                    float4 A = rp[0], B = rp[1];                              \
                    a[rr*4+0] = fmaf(A.x, tq.x, a[rr*4+0]); a[rr*4+1] = fmaf(A.y, tq.x, a[rr*4+1]); \
                    a[rr*4+2] = fmaf(A.z, tq.x, a[rr*4+2]); a[rr*4+3] = fmaf(A.w, tq.x, a[rr*4+3]); \
                    a[rr*4+0] = fmaf(A.y, tq.y, a[rr*4+0]); a[rr*4+1] = fmaf(A.z, tq.y, a[rr*4+1]); \
                    a[rr*4+2] = fmaf(A.w, tq.y, a[rr*4+2]); a[rr*4+3] = fmaf(B.x, tq.y, a[rr*4+3]); \
                    a[rr*4+0] = fmaf(A.z, tq.z, a[rr*4+0]); a[rr*4+1] = fmaf(A.w, tq.z, a[rr*4+1]); \
                    a[rr*4+2] = fmaf(B.x, tq.z, a[rr*4+2]); a[rr*4+3] = fmaf(B.y, tq.z, a[rr*4+3]); \
                    a[rr*4+0] = fmaf(A.w, tq.w, a[rr*4+0]); a[rr*4+1] = fmaf(B.x, tq.w, a[rr*4+1]); \
                    a[rr*4+2] = fmaf(B.y, tq.w, a[rr*4+2]); a[rr*4+3] = fmaf(B.z, tq.w, a[rr*4+3]); \
                    a[rr*4+0] = fmaf(B.x, t4v, a[rr*4+0]); a[rr*4+1] = fmaf(B.y, t4v, a[rr*4+1]); \
                    a[rr*4+2] = fmaf(B.z, t4v, a[rr*4+2]); a[rr*4+3] = fmaf(B.w, t4v, a[rr*4+3]); \
                }                                                             \
            }                                                                 \
            _Pragma("unroll")                                                 \
            for (int rr = 0; rr < 3; rr++) {                                  \
                float4 usv = *(const float4*)&sUS[(ffr0 + rr) * RS + ffc0];   \
                float us[4] = {usv.x, usv.y, usv.z, usv.w};                   \
                float res[4];                                                 \
                _Pragma("unroll")                                             \
                for (int k = 0; k < 4; k++) {                                 \
                    float xc = fminf(fmaxf(a[rr * 4 + k], XMIN), XMAX);       \
                    float tt = (xc - XMIN) * LUT_INVH;                        \
                    int ii = (int)tt;                                         \
                    ii = min(ii, NCELL - 1);                                  \
                    float frac = tt - (float)ii;                              \
                    float2 cell = sLUT[ii];                                   \
                    res[k] = us[k] * fmaf(cell.y, frac, cell.x);              \
                }                                                             \
                *(float4*)&(DST)[(ffr0 + rr) * RS + ffc0] =                   \
                    make_float4(res[0], res[1], res[2], res[3]);              \
            }                                                                 \
        }

    // ---- adjoint: flipped 5x5 conv; taps reversed in registers ----
    #define ADJ(FI, SRC)                                                      \
        {                                                                     \
            const float* Fp = &sF[(FI) * 40];                                 \
            float a[8];                                                       \
            _Pragma("unroll")                                                 \
            for (int k = 0; k < 8; k++) a[k] = 0.f;                           \
            _Pragma("unroll")                                                 \
            for (int ky = 0; ky < 5; ky++) {                                  \
                float4 tq = *(const float4*)&Fp[(4 - ky) * 8];                \
                float tr0 = Fp[(4 - ky) * 8 + 4];                             \
                float tr1 = tq.w, tr2 = tq.z, tr3 = tq.y, tr4 = tq.x;         \
                _Pragma("unroll")                                             \
                for (int rr = 0; rr < 2; rr++) {                              \
                    const float4* rp = (const float4*)&(SRC)[(qr0 + rr + ky) * RS + qc0]; \
                    float4 A = rp[0], B = rp[1];                              \
                    a[rr*4+0] = fmaf(A.x, tr0, a[rr*4+0]); a[rr*4+1] = fmaf(A.y, tr0, a[rr*4+1]); \
                    a[rr*4+2] = fmaf(A.z, tr0, a[rr*4+2]); a[rr*4+3] = fmaf(A.w, tr0, a[rr*4+3]); \
                    a[rr*4+0] = fmaf(A.y, tr1, a[rr*4+0]); a[rr*4+1] = fmaf(A.z, tr1, a[rr*4+1]); \
                    a[rr*4+2] = fmaf(A.w, tr1, a[rr*4+2]); a[rr*4+3] = fmaf(B.x, tr1, a[rr*4+3]); \
                    a[rr*4+0] = fmaf(A.z, tr2, a[rr*4+0]); a[rr*4+1] = fmaf(A.w, tr2, a[rr*4+1]); \
                    a[rr*4+2] = fmaf(B.x, tr2, a[rr*4+2]); a[rr*4+3] = fmaf(B.y, tr2, a[rr*4+3]); \
                    a[rr*4+0] = fmaf(A.w, tr3, a[rr*4+0]); a[rr*4+1] = fmaf(B.x, tr3, a[rr*4+1]); \
                    a[rr*4+2] = fmaf(B.y, tr3, a[rr*4+2]); a[rr*4+3] = fmaf(B.z, tr3, a[rr*4+3]); \
                    a[rr*4+0] = fmaf(B.x, tr4, a[rr*4+0]); a[rr*4+1] = fmaf(B.y, tr4, a[rr*4+1]); \
                    a[rr*4+2] = fmaf(B.z, tr4, a[rr*4+2]); a[rr*4+3] = fmaf(B.w, tr4, a[rr*4+3]); \
                }                                                             \
            }                                                                 \
            _Pragma("unroll")                                                 \
            for (int k = 0; k < 8; k++) acc[k] += a[k];                       \
        }

    // ---- pipelined loop: 1 named barrier per filter ----
    FWD(fbase + 0, phiBuf[0])
    GBAR();
    #pragma unroll 1
    for (int kf = 1; kf < NFG; kf++) {
        FWD(fbase + kf, phiBuf[kf & 1])
        ADJ(fbase + kf - 1, phiBuf[(kf - 1) & 1])
        GBAR();
    }
    ADJ(fbase + NFG - 1, phiBuf[(NFG - 1) & 1])
    #undef FWD
    #undef ADJ
    #undef GBAR

    // ---- combine group accumulators (groups 1..3 -> smem; group 0 sums) ----
    __syncthreads();                 // all groups done with their phi buffers
    if (g > 0) {
        float4* buf = (float4*)(smem + OFF_PHI + (2 * g) * PHI_STRIDE);
        buf[gt * 2 + 0] = make_float4(acc[0], acc[1], acc[2], acc[3]);
        buf[gt * 2 + 1] = make_float4(acc[4], acc[5], acc[6], acc[7]);
    }
    __syncthreads();

    // ---- epilogue: reaction + clip (group 0) ----
    if (g == 0) {
        #pragma unroll
        for (int gg = 1; gg < 4; gg++) {
            const float4* buf = (const float4*)(smem + OFF_PHI + (2 * gg) * PHI_STRIDE);
            float4 c0 = buf[gt * 2 + 0], c1 = buf[gt * 2 + 1];
            acc[0] += c0.x; acc[1] += c0.y; acc[2] += c0.z; acc[3] += c0.w;
            acc[4] += c1.x; acc[5] += c1.y; acc[6] += c1.z; acc[7] += c1.w;
        }
        const float lambda = lam[0];
        #pragma unroll
        for (int rr = 0; rr < 2; rr++) {
            const int gy = oy0 + qr0 + rr;
            if (gy < IMH) {
                float4 uv4 = *(const float4*)&sU[(qr0 + rr + 4) * RS + qc0 + 4];
                float uvs[4] = {uv4.x, uv4.y, uv4.z, uv4.w};
                #pragma unroll
                for (int k = 0; k < 4; k++) {
                    int gx = ox0 + qc0 + k;
                    if (gx < IMW) {
                        float uv = uvs[k];
                        float fv = fb[gy * IMW + gx];
                        float reac = lambda * (uv - fv) / (uv * uv + 1e-3f);
                        float o = uv - acc[rr * 4 + k] - reac;
                        o = fminf(fmaxf(o, 0.f), 1.f);
                        ob[gy * IMW + gx] = o;
                    }
                }
            }
        }
    }
}

// ---------------------------------------------------------------------------
// Launch
// ---------------------------------------------------------------------------
extern "C" void kernel_launch(void* const* d_in, const int* in_sizes, int n_in,
                              void* d_out, int out_size) {
    const float* u    = (const float*)d_in[0];
    const float* f    = (const float*)d_in[1];
    const float* filt = (const float*)d_in[2];
    const float* lam  = (const float*)d_in[3];
    const float* mu   = (const float*)d_in[4];
    const float* wts  = (const float*)d_in[5];
    float* out = (float*)d_out;

    // SMEM_BYTES > 48KB needs the opt-in attribute. Set once, outside graph
    // capture (the harness's correctness call precedes capture).
    static bool attr_set = false;
    if (!attr_set) {
        cudaFuncSetAttribute(k_main, cudaFuncAttributeMaxDynamicSharedMemorySize,
                             SMEM_BYTES);
        attr_set = true;
    }

    k_init<<<68, 256>>>(u, mu, wts);
    dim3 grid((IMW + TILE - 1) / TILE, (IMH + TILE - 1) / TILE, BATCH);
    k_main<<<grid, NTHR, SMEM_BYTES>>>(u, f, filt, lam, out);
}